// round 1
// baseline (speedup 1.0000x reference)
#include <cuda_runtime.h>
#include <cuda_bf16.h>

// Problem constants (match reference setup_inputs)
#define N_NODES_MAX  50000
#define N_HEDGES_MAX 20000
#define N_EDGES_MAX  800000
#define DMODEL 128
#define NHEAD 4
#define HDIM 32   // head dim

// ---------------- scratch (static device globals; no runtime allocation) ----
__device__ float g_Q[N_NODES_MAX * DMODEL];     // 25.6 MB
__device__ float g_K[N_HEDGES_MAX * DMODEL];    // 10.2 MB
__device__ float g_V[N_HEDGES_MAX * DMODEL];    // 10.2 MB
__device__ float g_E[N_EDGES_MAX * NHEAD];      // 12.8 MB  exp(score)
__device__ float g_Z[N_NODES_MAX * NHEAD];      //  0.8 MB  softmax denom
__device__ float g_A[N_NODES_MAX * DMODEL];     // 25.6 MB  attention accumulator

// ---------------- zero init -------------------------------------------------
__global__ void zero_kernel(float* __restrict__ z, float* __restrict__ acc, int N) {
    int i = blockIdx.x * blockDim.x + threadIdx.x;
    int tot = N * DMODEL;
    if (i < N * NHEAD) z[i] = 0.0f;
    if (i < tot) acc[i] = 0.0f;
}

// ---------------- GEMM: Y[M,128] = X[M,128] @ W[128,128] + b (+resid) -------
// Block: 256 threads, 64 rows x 128 cols. W fully staged in shared (64 KB),
// A tile 64x128 (32 KB). Thread computes 8 rows x 4 cols.
__global__ void gemm128(const float* __restrict__ X, const float* __restrict__ W,
                        const float* __restrict__ bias, const float* __restrict__ resid,
                        float* __restrict__ Y, int M) {
    extern __shared__ float smem[];
    float* sA = smem;                // 64*128 floats
    float* sW = smem + 64 * DMODEL;  // 128*128 floats

    int tid = threadIdx.x;
    int row0 = blockIdx.x * 64;

    float4* sW4 = (float4*)sW;
    const float4* W4 = (const float4*)W;
#pragma unroll
    for (int i = 0; i < 16; i++) sW4[tid + i * 256] = W4[tid + i * 256];

    float4* sA4 = (float4*)sA;
    const float4* X4 = (const float4*)X;
#pragma unroll
    for (int i = 0; i < 8; i++) {
        int idx = tid + i * 256;            // 0..2047
        int r = idx >> 5;
        float4 v = make_float4(0.f, 0.f, 0.f, 0.f);
        if (row0 + r < M) v = X4[(row0 + r) * 32 + (idx & 31)];
        sA4[idx] = v;
    }
    __syncthreads();

    int rbase = (tid >> 5) * 8;
    int c4 = tid & 31;
    float acc[8][4];
#pragma unroll
    for (int r = 0; r < 8; r++) {
        acc[r][0] = acc[r][1] = acc[r][2] = acc[r][3] = 0.f;
    }

#pragma unroll 4
    for (int k = 0; k < DMODEL; k++) {
        float4 w = sW4[k * 32 + c4];
#pragma unroll
        for (int r = 0; r < 8; r++) {
            float a = sA[(rbase + r) * DMODEL + k];
            acc[r][0] = fmaf(a, w.x, acc[r][0]);
            acc[r][1] = fmaf(a, w.y, acc[r][1]);
            acc[r][2] = fmaf(a, w.z, acc[r][2]);
            acc[r][3] = fmaf(a, w.w, acc[r][3]);
        }
    }

    float4 b4 = ((const float4*)bias)[c4];
#pragma unroll
    for (int r = 0; r < 8; r++) {
        int row = row0 + rbase + r;
        if (row < M) {
            float4 o;
            o.x = acc[r][0] + b4.x;
            o.y = acc[r][1] + b4.y;
            o.z = acc[r][2] + b4.z;
            o.w = acc[r][3] + b4.w;
            if (resid) {
                float4 rr = ((const float4*)resid)[row * 32 + c4];
                o.x += rr.x; o.y += rr.y; o.z += rr.z; o.w += rr.w;
            }
            ((float4*)Y)[row * 32 + c4] = o;
        }
    }
}

// ---------------- edge pass 1: scores -> exp -> z ---------------------------
// One warp per edge. Lane l handles floats [4l,4l+3]; head = l/8.
// exp(score) without segment-max: scores ~ N(0,1), max over 3.2M ~5.5 -> safe,
// and exp(s)/sum(exp(s)) == exp(s-m)/sum(exp(s-m)) exactly (mathematically).
__global__ void edge_pass1(const float4* __restrict__ Q, const float4* __restrict__ K,
                           const int* __restrict__ src, const int* __restrict__ dst,
                           float* __restrict__ esc, float* __restrict__ z, int E) {
    int w = (blockIdx.x * blockDim.x + threadIdx.x) >> 5;
    int lane = threadIdx.x & 31;
    if (w >= E) return;
    int s = src[w];
    int d = dst[w];
    float4 q = Q[s * 32 + lane];
    float4 k = K[d * 32 + lane];
    float p = q.x * k.x + q.y * k.y + q.z * k.z + q.w * k.w;
    // reduce within each 8-lane head group
    p += __shfl_xor_sync(0xffffffffu, p, 1);
    p += __shfl_xor_sync(0xffffffffu, p, 2);
    p += __shfl_xor_sync(0xffffffffu, p, 4);
    if ((lane & 7) == 0) {
        int h = lane >> 3;
        float ev = expf(p * 0.17677669529663687f);  // 1/sqrt(32)
        esc[w * NHEAD + h] = ev;
        atomicAdd(&z[s * NHEAD + h], ev);
    }
}

// ---------------- edge pass 2: weighted scatter of V ------------------------
// One warp per edge. w = e/z for the lane's head; red.v4 into acc[src].
__global__ void edge_pass2(const float* __restrict__ esc, const float* __restrict__ z,
                           const float4* __restrict__ V,
                           const int* __restrict__ src, const int* __restrict__ dst,
                           float* __restrict__ acc, int E) {
    int w = (blockIdx.x * blockDim.x + threadIdx.x) >> 5;
    int lane = threadIdx.x & 31;
    if (w >= E) return;
    int s = src[w];
    int d = dst[w];
    int h = lane >> 3;
    float ww = esc[w * NHEAD + h] / z[s * NHEAD + h];
    float4 v = V[d * 32 + lane];
    float* p = acc + s * DMODEL + lane * 4;
    asm volatile("red.global.add.v4.f32 [%0], {%1, %2, %3, %4};"
                 :: "l"(p), "f"(v.x * ww), "f"(v.y * ww), "f"(v.z * ww), "f"(v.w * ww)
                 : "memory");
}

// ---------------- launch ----------------------------------------------------
extern "C" void kernel_launch(void* const* d_in, const int* in_sizes, int n_in,
                              void* d_out, int out_size) {
    const float* x_node = (const float*)d_in[0];
    const float* x_edge = (const float*)d_in[1];
    const int*   src    = (const int*)d_in[2];
    const int*   dst    = (const int*)d_in[3];
    const float* Wq     = (const float*)d_in[4];
    const float* bq     = (const float*)d_in[5];
    const float* Wk     = (const float*)d_in[6];
    const float* bk     = (const float*)d_in[7];
    const float* Wv     = (const float*)d_in[8];
    const float* bv     = (const float*)d_in[9];
    const float* Wo     = (const float*)d_in[10];
    const float* bo     = (const float*)d_in[11];
    float* out = (float*)d_out;

    int N  = in_sizes[0] / DMODEL;   // 50000
    int NH = in_sizes[1] / DMODEL;   // 20000
    int E  = in_sizes[2];            // 800000

    float *Qp, *Kp, *Vp, *Ep, *Zp, *Ap;
    cudaGetSymbolAddress((void**)&Qp, g_Q);
    cudaGetSymbolAddress((void**)&Kp, g_K);
    cudaGetSymbolAddress((void**)&Vp, g_V);
    cudaGetSymbolAddress((void**)&Ep, g_E);
    cudaGetSymbolAddress((void**)&Zp, g_Z);
    cudaGetSymbolAddress((void**)&Ap, g_A);

    const int SMEM = (64 * DMODEL + DMODEL * DMODEL) * sizeof(float);  // 96 KB
    cudaFuncSetAttribute(gemm128, cudaFuncAttributeMaxDynamicSharedMemorySize, SMEM);

    // 1. zero z + acc
    {
        int tot = N * DMODEL;
        zero_kernel<<<(tot + 255) / 256, 256>>>(Zp, Ap, N);
    }
    // 2-4. Q/K/V projections
    gemm128<<<(N + 63) / 64, 256, SMEM>>>(x_node, Wq, bq, nullptr, Qp, N);
    gemm128<<<(NH + 63) / 64, 256, SMEM>>>(x_edge, Wk, bk, nullptr, Kp, NH);
    gemm128<<<(NH + 63) / 64, 256, SMEM>>>(x_edge, Wv, bv, nullptr, Vp, NH);
    // 5. scores + softmax denominator
    {
        int nthreads = E * 32;
        edge_pass1<<<(nthreads + 255) / 256, 256>>>((const float4*)Qp, (const float4*)Kp,
                                                    src, dst, Ep, Zp, E);
    }
    // 6. weighted scatter of V messages
    {
        int nthreads = E * 32;
        edge_pass2<<<(nthreads + 255) / 256, 256>>>(Ep, Zp, (const float4*)Vp,
                                                    src, dst, Ap, E);
    }
    // 7. output projection + bias + residual -> d_out
    gemm128<<<(N + 63) / 64, 256, SMEM>>>(Ap, Wo, bo, x_node, out, N);
}

// round 3
// speedup vs baseline: 1.4232x; 1.4232x over previous
#include <cuda_runtime.h>
#include <cuda_bf16.h>

#define N_NODES_MAX  50000
#define N_HEDGES_MAX 20000
#define N_EDGES_MAX  800000
#define DMODEL 128
#define NHEAD 4

// ---------------- scratch (static device globals) ---------------------------
__device__ float g_Q[N_NODES_MAX * DMODEL];      // 25.6 MB
__device__ float g_K[N_HEDGES_MAX * DMODEL];     // 10.2 MB
__device__ float g_V[N_HEDGES_MAX * DMODEL];     // 10.2 MB
__device__ float g_A[N_NODES_MAX * DMODEL];      // 25.6 MB (normalized attn out)
__device__ int   g_cnt[N_NODES_MAX];             // degree histogram
__device__ int   g_cur[N_NODES_MAX];             // scatter cursor
__device__ int   g_off[N_NODES_MAX + 1];         // CSR offsets
__device__ int   g_bsum[256];                    // scan block sums
__device__ int   g_dstc[N_EDGES_MAX];            // CSR-ordered dst (compacted)

// ---------------- zero cnt + cur --------------------------------------------
__global__ void zero_kernel(int* __restrict__ cnt, int* __restrict__ cur, int N) {
    int i = blockIdx.x * blockDim.x + threadIdx.x;
    if (i < N) { cnt[i] = 0; cur[i] = 0; }
}

// ---------------- CSR build: histogram --------------------------------------
__global__ void hist_kernel(const int* __restrict__ src, int* __restrict__ cnt, int E) {
    int e = blockIdx.x * blockDim.x + threadIdx.x;
    if (e < E) atomicAdd(&cnt[src[e]], 1);
}

// ---------------- CSR build: 3-step exclusive scan --------------------------
__global__ void scan1_kernel(const int* __restrict__ cnt, int* __restrict__ off,
                             int* __restrict__ bsum, int n) {
    __shared__ int s[256];
    int tid = threadIdx.x;
    int i = blockIdx.x * 256 + tid;
    int v = (i < n) ? cnt[i] : 0;
    s[tid] = v;
    __syncthreads();
#pragma unroll
    for (int d = 1; d < 256; d <<= 1) {
        int t = 0;
        if (tid >= d) t = s[tid - d];
        __syncthreads();
        if (tid >= d) s[tid] += t;
        __syncthreads();
    }
    if (i < n) off[i] = s[tid] - v;          // exclusive within block
    if (tid == 255) bsum[blockIdx.x] = s[255];
}

__global__ void scan2_kernel(int* __restrict__ bsum, int nb) {
    __shared__ int s[256];
    int tid = threadIdx.x;
    int v = (tid < nb) ? bsum[tid] : 0;
    s[tid] = v;
    __syncthreads();
#pragma unroll
    for (int d = 1; d < 256; d <<= 1) {
        int t = 0;
        if (tid >= d) t = s[tid - d];
        __syncthreads();
        if (tid >= d) s[tid] += t;
        __syncthreads();
    }
    if (tid < nb) bsum[tid] = s[tid] - v;    // exclusive block offsets
}

__global__ void scan3_kernel(int* __restrict__ off, const int* __restrict__ bsum,
                             int n, int E) {
    int i = blockIdx.x * blockDim.x + threadIdx.x;
    if (i < n) off[i] += bsum[i >> 8];
    if (i == 0) off[n] = E;
}

// ---------------- CSR build: scatter dst (compacted by src) ------------------
__global__ void scatter_kernel(const int* __restrict__ src, const int* __restrict__ dst,
                               const int* __restrict__ off,
                               int* __restrict__ cur, int* __restrict__ dstc, int E) {
    int e = blockIdx.x * blockDim.x + threadIdx.x;
    if (e < E) {
        int s = src[e];
        int p = off[s] + atomicAdd(&cur[s], 1);
        dstc[p] = dst[e];
    }
}

// ---------------- GEMM: Y[M,128] = X[M,128] @ W[128,128] + b (+resid) -------
// 128x128 tile, 256 threads, 8x8 per thread. W + A fully staged in smem.
#define SA 132
#define SW 132
__global__ void gemm128(const float* __restrict__ X, const float* __restrict__ W,
                        const float* __restrict__ bias, const float* __restrict__ resid,
                        float* __restrict__ Y, int M) {
    extern __shared__ float smem[];
    float* sA = smem;                // 128 * SA
    float* sW = smem + 128 * SA;     // 128 * SW

    int tid = threadIdx.x;
    int row0 = blockIdx.x * 128;

    const float4* W4 = (const float4*)W;
    const float4* X4 = (const float4*)X;
#pragma unroll
    for (int i = 0; i < 16; i++) {
        int idx = tid + i * 256;         // 0..4095
        int r = idx >> 5, c4 = idx & 31;
        *(float4*)&sW[r * SW + c4 * 4] = W4[idx];
        float4 v = make_float4(0.f, 0.f, 0.f, 0.f);
        if (row0 + r < M) v = X4[(row0 + r) * 32 + c4];
        *(float4*)&sA[r * SA + c4 * 4] = v;
    }
    __syncthreads();

    int tr = tid >> 4, tc = tid & 15;
    int r0 = tr * 8, c0 = tc * 8;
    float acc[8][8];
#pragma unroll
    for (int i = 0; i < 8; i++)
#pragma unroll
        for (int j = 0; j < 8; j++) acc[i][j] = 0.f;

#pragma unroll 4
    for (int k = 0; k < DMODEL; k++) {
        float w[8], a[8];
        float4 w0 = *(float4*)&sW[k * SW + c0];
        float4 w1 = *(float4*)&sW[k * SW + c0 + 4];
        w[0] = w0.x; w[1] = w0.y; w[2] = w0.z; w[3] = w0.w;
        w[4] = w1.x; w[5] = w1.y; w[6] = w1.z; w[7] = w1.w;
#pragma unroll
        for (int i = 0; i < 8; i++) a[i] = sA[(r0 + i) * SA + k];
#pragma unroll
        for (int i = 0; i < 8; i++)
#pragma unroll
            for (int j = 0; j < 8; j++)
                acc[i][j] = fmaf(a[i], w[j], acc[i][j]);
    }

    float4 b0 = ((const float4*)bias)[tc * 2];
    float4 b1 = ((const float4*)bias)[tc * 2 + 1];
#pragma unroll
    for (int i = 0; i < 8; i++) {
        int row = row0 + r0 + i;
        if (row < M) {
            float4 o0 = make_float4(acc[i][0] + b0.x, acc[i][1] + b0.y,
                                    acc[i][2] + b0.z, acc[i][3] + b0.w);
            float4 o1 = make_float4(acc[i][4] + b1.x, acc[i][5] + b1.y,
                                    acc[i][6] + b1.z, acc[i][7] + b1.w);
            if (resid) {
                float4 r0v = ((const float4*)resid)[row * 32 + tc * 2];
                float4 r1v = ((const float4*)resid)[row * 32 + tc * 2 + 1];
                o0.x += r0v.x; o0.y += r0v.y; o0.z += r0v.z; o0.w += r0v.w;
                o1.x += r1v.x; o1.y += r1v.y; o1.z += r1v.z; o1.w += r1v.w;
            }
            ((float4*)Y)[row * 32 + tc * 2] = o0;
            ((float4*)Y)[row * 32 + tc * 2 + 1] = o1;
        }
    }
}

// ---------------- gather attention: one warp per node -----------------------
// Single pass: acc += exp(score)*V, z += exp(score); out = acc/z.
// (No segment-max: exp(s)/sum exp(s) is mathematically identical; scores ~N(0,1)
//  so exp cannot overflow.)
// Per-warp dst indices staged in smem so K/V loads of consecutive edges can be
// front-batched by ptxas (higher MLP on the L2-resident gathers).
__global__ void gather_attn(const float4* __restrict__ Q, const float4* __restrict__ K,
                            const float4* __restrict__ V,
                            const int* __restrict__ off, const int* __restrict__ dstc,
                            float4* __restrict__ A, int N) {
    __shared__ int sidx[8][32];          // 8 warps per block
    int warp_in_blk = threadIdx.x >> 5;
    int w = blockIdx.x * 8 + warp_in_blk;
    int lane = threadIdx.x & 31;
    if (w >= N) return;

    int e0 = off[w];
    int e1 = off[w + 1];
    float4 q = Q[w * 32 + lane];
    float4 acc = make_float4(0.f, 0.f, 0.f, 0.f);
    float z = 0.f;
    int* my = sidx[warp_in_blk];

    for (int base = e0; base < e1; base += 32) {
        int cnt = min(32, e1 - base);
        if (lane < cnt) my[lane] = dstc[base + lane];
        __syncwarp();
#pragma unroll 2
        for (int j = 0; j < cnt; j++) {
            int d = my[j];
            float4 k4 = K[d * 32 + lane];
            float4 v4 = V[d * 32 + lane];
            float p = q.x * k4.x + q.y * k4.y + q.z * k4.z + q.w * k4.w;
            p += __shfl_xor_sync(0xffffffffu, p, 1);
            p += __shfl_xor_sync(0xffffffffu, p, 2);
            p += __shfl_xor_sync(0xffffffffu, p, 4);
            float ev = __expf(p * 0.17677669529663687f);   // 1/sqrt(32)
            acc.x = fmaf(ev, v4.x, acc.x); acc.y = fmaf(ev, v4.y, acc.y);
            acc.z = fmaf(ev, v4.z, acc.z); acc.w = fmaf(ev, v4.w, acc.w);
            z += ev;
        }
        __syncwarp();
    }
    float inv = (z > 0.f) ? 1.f / z : 0.f;
    acc.x *= inv; acc.y *= inv; acc.z *= inv; acc.w *= inv;
    A[w * 32 + lane] = acc;
}

// ---------------- launch ----------------------------------------------------
extern "C" void kernel_launch(void* const* d_in, const int* in_sizes, int n_in,
                              void* d_out, int out_size) {
    const float* x_node = (const float*)d_in[0];
    const float* x_edge = (const float*)d_in[1];
    const int*   src    = (const int*)d_in[2];
    const int*   dst    = (const int*)d_in[3];
    const float* Wq     = (const float*)d_in[4];
    const float* bq     = (const float*)d_in[5];
    const float* Wk     = (const float*)d_in[6];
    const float* bk     = (const float*)d_in[7];
    const float* Wv     = (const float*)d_in[8];
    const float* bv     = (const float*)d_in[9];
    const float* Wo     = (const float*)d_in[10];
    const float* bo     = (const float*)d_in[11];
    float* out = (float*)d_out;

    int N  = in_sizes[0] / DMODEL;   // 50000
    int NH = in_sizes[1] / DMODEL;   // 20000
    int E  = in_sizes[2];            // 800000

    float *Qp, *Kp, *Vp, *Ap;
    int *cntp, *curp, *offp, *bsump, *dstcp;
    cudaGetSymbolAddress((void**)&Qp, g_Q);
    cudaGetSymbolAddress((void**)&Kp, g_K);
    cudaGetSymbolAddress((void**)&Vp, g_V);
    cudaGetSymbolAddress((void**)&Ap, g_A);
    cudaGetSymbolAddress((void**)&cntp, g_cnt);
    cudaGetSymbolAddress((void**)&curp, g_cur);
    cudaGetSymbolAddress((void**)&offp, g_off);
    cudaGetSymbolAddress((void**)&bsump, g_bsum);
    cudaGetSymbolAddress((void**)&dstcp, g_dstc);

    const int SMEM = (128 * SA + 128 * SW) * sizeof(float);  // 132 KB
    cudaFuncSetAttribute(gemm128, cudaFuncAttributeMaxDynamicSharedMemorySize, SMEM);

    int nb = (N + 255) / 256;  // scan blocks (196 for N=50000)

    // CSR build
    zero_kernel<<<nb, 256>>>(cntp, curp, N);
    hist_kernel<<<(E + 255) / 256, 256>>>(src, cntp, E);
    scan1_kernel<<<nb, 256>>>(cntp, offp, bsump, N);
    scan2_kernel<<<1, 256>>>(bsump, nb);
    scan3_kernel<<<nb, 256>>>(offp, bsump, N, E);
    scatter_kernel<<<(E + 255) / 256, 256>>>(src, dst, offp, curp, dstcp, E);

    // Projections
    gemm128<<<(N + 127) / 128, 256, SMEM>>>(x_node, Wq, bq, nullptr, Qp, N);
    gemm128<<<(NH + 127) / 128, 256, SMEM>>>(x_edge, Wk, bk, nullptr, Kp, NH);
    gemm128<<<(NH + 127) / 128, 256, SMEM>>>(x_edge, Wv, bv, nullptr, Vp, NH);

    // Attention gather (warp per node, 8 warps per block)
    gather_attn<<<(N + 7) / 8, 256>>>((const float4*)Qp, (const float4*)Kp,
                                      (const float4*)Vp, offp, dstcp,
                                      (float4*)Ap, N);

    // Output projection + bias + residual
    gemm128<<<(N + 127) / 128, 256, SMEM>>>(Ap, Wo, bo, x_node, out, N);
}